// round 5
// baseline (speedup 1.0000x reference)
#include <cuda_runtime.h>
#include <math.h>

// Problem constants
#define B_ 8
#define L_ 512
#define K_ 512
#define D_ 64
#define M_ 64
#define N_ 64
#define P_ 64

// Scratch for vkc = einsum('bkpn,bkp->bkn', vk, vexp): 8*512*64 floats = 1 MB
__device__ float g_vkc[B_ * K_ * N_];

// ---------------------------------------------------------------------------
// Kernel 1: vkc[b,k,n] = sum_p vk[b,k,p,n] * vexp[b,k,p]
// grid = B*K blocks, 64 threads (one per n). Loads of vk are n-contiguous ->
// fully coalesced; vexp row staged in smem.
// ---------------------------------------------------------------------------
__global__ __launch_bounds__(64) void vkc_kernel(const float* __restrict__ vk,
                                                 const float* __restrict__ vexp) {
    const int bk = blockIdx.x;      // b*K_ + k
    const int n = threadIdx.x;      // 0..63

    __shared__ float se[P_];
    se[n] = vexp[(size_t)bk * P_ + n];
    __syncthreads();

    const float* base = vk + (size_t)bk * P_ * N_ + n;
    float acc = 0.f;
#pragma unroll
    for (int p = 0; p < P_; ++p) {
        acc = fmaf(base[p * N_], se[p], acc);
    }
    g_vkc[(size_t)bk * N_ + n] = acc;
}

// ---------------------------------------------------------------------------
// Kernel 2: fused attention row. One block per (b,l), 256 threads.
//   scores[k] = scale * q[b,l,:] . k[b,k,:]         (each thread: 2 k-rows)
//   softmax over K (unnormalized exp kept; 1/sum folded later)
//   tmp[n]    = (1/sum) * sum_k e[k] * vkc[b,k,n]   (4-way k split, coalesced n)
//   attn[m]   = sum_n vq[b,l,m,n] * tmp[n]
//   out       = LayerNorm(q + attn) with gamma/beta, eps=1e-3
// ---------------------------------------------------------------------------
__global__ __launch_bounds__(256) void attn_kernel(const float* __restrict__ q,
                                                   const float* __restrict__ kmat,
                                                   const float* __restrict__ vq,
                                                   const float* __restrict__ scale_p,
                                                   const float* __restrict__ gamma,
                                                   const float* __restrict__ beta,
                                                   float* __restrict__ out) {
    const int bl = blockIdx.x;          // b*L_ + l
    const int b = bl >> 9;              // / 512
    const int t = threadIdx.x;
    const int warp = t >> 5;
    const int lane = t & 31;

    __shared__ float sq[D_];            // q row
    __shared__ float sw[K_];            // exp(scores - max)
    __shared__ float stmp[N_];          // tmp vector
    __shared__ float spart[4][N_];      // partial tmp per k-quarter
    __shared__ float sred[16];          // cross-warp reduction scratch

    const float scl = *scale_p;

    // Load q row into smem
    if (t < D_) sq[t] = q[(size_t)bl * D_ + t];
    __syncthreads();

    // ---- scores: thread handles k-indices t and t+256 ----
    const float4* q4 = (const float4*)sq;
    float s0 = 0.f, s1 = 0.f;
    {
        const float4* k0 = (const float4*)(kmat + ((size_t)b * K_ + t) * D_);
        const float4* k1 = (const float4*)(kmat + ((size_t)b * K_ + t + 256) * D_);
#pragma unroll
        for (int i = 0; i < D_ / 4; ++i) {
            float4 qv = q4[i];
            float4 a = k0[i];
            float4 c = k1[i];
            s0 = fmaf(qv.x, a.x, s0); s0 = fmaf(qv.y, a.y, s0);
            s0 = fmaf(qv.z, a.z, s0); s0 = fmaf(qv.w, a.w, s0);
            s1 = fmaf(qv.x, c.x, s1); s1 = fmaf(qv.y, c.y, s1);
            s1 = fmaf(qv.z, c.z, s1); s1 = fmaf(qv.w, c.w, s1);
        }
    }
    s0 *= scl;
    s1 *= scl;

    // ---- max reduce over 512 scores ----
    float mx = fmaxf(s0, s1);
#pragma unroll
    for (int o = 16; o; o >>= 1) mx = fmaxf(mx, __shfl_xor_sync(0xFFFFFFFFu, mx, o));
    if (lane == 0) sred[warp] = mx;
    __syncthreads();
    if (t == 0) {
        float m = sred[0];
#pragma unroll
        for (int w = 1; w < 8; ++w) m = fmaxf(m, sred[w]);
        sred[8] = m;
    }
    __syncthreads();
    mx = sred[8];

    // ---- exp + sum ----
    float e0 = __expf(s0 - mx);
    float e1 = __expf(s1 - mx);
    sw[t] = e0;
    sw[t + 256] = e1;
    float sum = e0 + e1;
#pragma unroll
    for (int o = 16; o; o >>= 1) sum += __shfl_xor_sync(0xFFFFFFFFu, sum, o);
    __syncthreads();           // protect sred reuse
    if (lane == 0) sred[warp] = sum;
    __syncthreads();
    if (t == 0) {
        float s = 0.f;
#pragma unroll
        for (int w = 0; w < 8; ++w) s += sred[w];
        sred[8] = 1.f / s;
    }
    __syncthreads();
    const float inv = sred[8];

    // ---- tmp[n] = inv * sum_k e[k] * vkc[b,k,n] ; 4-way split over k ----
    {
        const int n = t & 63;
        const int quart = t >> 6;       // 0..3, 128 k's each
        const float* vkcb = g_vkc + ((size_t)b * K_ + quart * 128) * N_ + n;
        const float* swq = sw + quart * 128;
        float acc = 0.f;
#pragma unroll 8
        for (int kk = 0; kk < 128; ++kk) {
            acc = fmaf(swq[kk], vkcb[(size_t)kk * N_], acc);
        }
        spart[quart][n] = acc;
    }
    __syncthreads();
    if (t < N_) {
        stmp[t] = (spart[0][t] + spart[1][t] + spart[2][t] + spart[3][t]) * inv;
    }
    __syncthreads();

    // ---- attn[m] + residual + LayerNorm over M=64 (threads 0..63, warps 0-1) ----
    float x = 0.f;
    if (t < M_) {
        const int m = t;
        const float4* vq4 = (const float4*)(vq + (((size_t)bl * M_) + m) * N_);
        const float4* t4 = (const float4*)stmp;
        float acc = 0.f;
#pragma unroll
        for (int i = 0; i < N_ / 4; ++i) {
            float4 a = vq4[i];
            float4 c = t4[i];
            acc = fmaf(a.x, c.x, acc); acc = fmaf(a.y, c.y, acc);
            acc = fmaf(a.z, c.z, acc); acc = fmaf(a.w, c.w, acc);
        }
        x = sq[m] + acc;   // residual

        float s = x, ss = x * x;
#pragma unroll
        for (int o = 16; o; o >>= 1) {
            s += __shfl_xor_sync(0xFFFFFFFFu, s, o);
            ss += __shfl_xor_sync(0xFFFFFFFFu, ss, o);
        }
        if (lane == 0) {
            sred[warp] = s;        // warp in {0,1}
            sred[warp + 8] = ss;
        }
    }
    __syncthreads();
    if (t < M_) {
        float s = sred[0] + sred[1];
        float ss = sred[8] + sred[9];
        const float mu = s * (1.f / 64.f);
        const float var = ss * (1.f / 64.f) - mu * mu;
        const float r = rsqrtf(var + 1e-3f);
        out[(size_t)bl * M_ + t] = (x - mu) * r * gamma[t] + beta[t];
    }
}

// ---------------------------------------------------------------------------
extern "C" void kernel_launch(void* const* d_in, const int* in_sizes, int n_in,
                              void* d_out, int out_size) {
    const float* q     = (const float*)d_in[0];
    const float* k     = (const float*)d_in[1];
    const float* vq    = (const float*)d_in[2];
    const float* vk    = (const float*)d_in[3];
    const float* vexp  = (const float*)d_in[4];
    const float* scale = (const float*)d_in[5];
    const float* gamma = (const float*)d_in[6];
    const float* beta  = (const float*)d_in[7];
    float* out = (float*)d_out;

    vkc_kernel<<<B_ * K_, 64>>>(vk, vexp);
    attn_kernel<<<B_ * L_, 256>>>(q, k, vq, scale, gamma, beta, out);
}

// round 6
// speedup vs baseline: 3.9526x; 3.9526x over previous
#include <cuda_runtime.h>
#include <math.h>

// Problem constants
#define B_ 8
#define L_ 512
#define K_ 512
#define D_ 64
#define M_ 64
#define N_ 64
#define P_ 64

#define TL 8           // l-rows per block
#define KC 64          // K-rows per smem chunk (Phase A)
#define SKSTRIDE 17    // sK row stride in float4 (68 floats -> conflict-free LDS.128)
#define SWSTRIDE 520   // sW row stride in floats (bank-skewed across rows)

// Scratch for vkc = einsum('bkpn,bkp->bkn', vk, vexp): 8*512*64 floats = 1 MB
__device__ float g_vkc[B_ * K_ * N_];

// ---------------------------------------------------------------------------
// Kernel 1: vkc[b,k,n] = sum_p vk[b,k,p,n] * vexp[b,k,p]   (streams vk once)
// ---------------------------------------------------------------------------
__global__ __launch_bounds__(64) void vkc_kernel(const float* __restrict__ vk,
                                                 const float* __restrict__ vexp) {
    const int bk = blockIdx.x;
    const int n = threadIdx.x;

    __shared__ float se[P_];
    se[n] = vexp[(size_t)bk * P_ + n];
    __syncthreads();

    const float* base = vk + (size_t)bk * P_ * N_ + n;
    float acc = 0.f;
#pragma unroll
    for (int p = 0; p < P_; ++p) {
        acc = fmaf(base[p * N_], se[p], acc);
    }
    g_vkc[(size_t)bk * N_ + n] = acc;
}

// ---------------------------------------------------------------------------
// Kernel 2: tiled fused attention. One block = 8 consecutive l-rows of one b.
// grid = B * L / TL = 512 blocks, 256 threads.
// ---------------------------------------------------------------------------
__global__ __launch_bounds__(256) void attn_kernel(const float* __restrict__ q,
                                                   const float* __restrict__ kmat,
                                                   const float* __restrict__ vq,
                                                   const float* __restrict__ scale_p,
                                                   const float* __restrict__ gamma,
                                                   const float* __restrict__ beta,
                                                   float* __restrict__ out) {
    __shared__ float4 sK4[KC * SKSTRIDE];       // 17408 B
    __shared__ float  sW[TL * SWSTRIDE];        // 16640 B  scores -> exp weights
    __shared__ float  sQ[TL * D_];              //  2048 B
    __shared__ float  sTmpP[2][TL * N_];        //  4096 B  k-half partials
    __shared__ float  sTmpF[TL * N_];           //  2048 B  final tmp
    __shared__ float  sAttn[TL * M_];           //  2048 B
    __shared__ float  sInv[TL];

    const int t = threadIdx.x;
    const int warp = t >> 5;
    const int lane = t & 31;
    const int blk = blockIdx.x;                 // b*64 + ltile
    const int b = blk >> 6;
    const int bl8 = blk * 8;                    // = b*L_ + ltile*8
    const float scl = *scale_p;

    // ---- load Q tile (8 rows x 64, contiguous) ----
    if (t < 128) ((float4*)sQ)[t] = ((const float4*)q)[(size_t)bl8 * 16 + t];
    __syncthreads();

    // ---- Phase A: scores S[l][k] = scale * q_l . k_k ----
    const int k_local = t & 63;
    const int lq = t >> 6;                      // 0..3 -> rows lq, lq+4
    const float4* kg4 = (const float4*)(kmat + (size_t)b * K_ * D_);
    const float4* qa = (const float4*)(sQ + lq * D_);
    const float4* qb = (const float4*)(sQ + (lq + 4) * D_);

    for (int c = 0; c < K_ / KC; ++c) {
        // cooperative coalesced load of 64 K-rows into padded smem
        for (int idx = t; idx < KC * 16; idx += 256) {
            int row = idx >> 4, c4 = idx & 15;
            sK4[row * SKSTRIDE + c4] = kg4[(size_t)(c * KC + row) * 16 + c4];
        }
        __syncthreads();

        float a0 = 0.f, a1 = 0.f;
#pragma unroll
        for (int d4 = 0; d4 < 16; ++d4) {
            float4 kv = sK4[k_local * SKSTRIDE + d4];
            float4 q0 = qa[d4];
            float4 q1 = qb[d4];
            a0 = fmaf(kv.x, q0.x, a0); a0 = fmaf(kv.y, q0.y, a0);
            a0 = fmaf(kv.z, q0.z, a0); a0 = fmaf(kv.w, q0.w, a0);
            a1 = fmaf(kv.x, q1.x, a1); a1 = fmaf(kv.y, q1.y, a1);
            a1 = fmaf(kv.z, q1.z, a1); a1 = fmaf(kv.w, q1.w, a1);
        }
        sW[lq * SWSTRIDE + c * KC + k_local] = a0 * scl;
        sW[(lq + 4) * SWSTRIDE + c * KC + k_local] = a1 * scl;
        __syncthreads();
    }

    // ---- softmax, warp w owns row w (no cross-warp reduction) ----
    {
        float* row = sW + warp * SWSTRIDE;
        float mx = -1e30f;
#pragma unroll
        for (int i = 0; i < K_ / 32; ++i) mx = fmaxf(mx, row[lane + i * 32]);
#pragma unroll
        for (int o = 16; o; o >>= 1) mx = fmaxf(mx, __shfl_xor_sync(0xFFFFFFFFu, mx, o));
        float s = 0.f;
#pragma unroll
        for (int i = 0; i < K_ / 32; ++i) {
            float e = __expf(row[lane + i * 32] - mx);
            row[lane + i * 32] = e;
            s += e;
        }
#pragma unroll
        for (int o = 16; o; o >>= 1) s += __shfl_xor_sync(0xFFFFFFFFu, s, o);
        if (lane == 0) sInv[warp] = 1.f / s;
    }
    __syncthreads();

    // ---- Phase B: tmp[l][n] = inv * sum_k e[l][k] * vkc[b][k][n] ----
    // thread: n4 = t&15 (float4 of n), l = (t>>4)&7, khalf = t>>7.
    // Lanes 0-15 and 16-31 read identical vkc addresses (HW dedup), each
    // LDG.128 warp-instruction covers 2 cache lines. vkc is L2-resident.
    {
        const int n4 = t & 15;
        const int l = (t >> 4) & 7;
        const int kh = t >> 7;
        const float4* vkc4 = (const float4*)(g_vkc + ((size_t)b * K_ + kh * 256) * N_) + n4;
        const float* wrow = sW + l * SWSTRIDE + kh * 256;
        float4 acc0 = make_float4(0.f, 0.f, 0.f, 0.f);
        float4 acc1 = make_float4(0.f, 0.f, 0.f, 0.f);
#pragma unroll 4
        for (int k = 0; k < 256; k += 2) {
            float w0 = wrow[k];
            float w1 = wrow[k + 1];
            float4 v0 = vkc4[(size_t)k * 16];
            float4 v1 = vkc4[(size_t)(k + 1) * 16];
            acc0.x = fmaf(w0, v0.x, acc0.x); acc0.y = fmaf(w0, v0.y, acc0.y);
            acc0.z = fmaf(w0, v0.z, acc0.z); acc0.w = fmaf(w0, v0.w, acc0.w);
            acc1.x = fmaf(w1, v1.x, acc1.x); acc1.y = fmaf(w1, v1.y, acc1.y);
            acc1.z = fmaf(w1, v1.z, acc1.z); acc1.w = fmaf(w1, v1.w, acc1.w);
        }
        float4 acc = make_float4(acc0.x + acc1.x, acc0.y + acc1.y,
                                 acc0.z + acc1.z, acc0.w + acc1.w);
        ((float4*)(sTmpP[kh] + l * N_))[n4] = acc;
    }
    __syncthreads();
    if (t < 128) {
        const int l = t >> 4, n4 = t & 15;
        float4 a = ((float4*)(sTmpP[0] + l * N_))[n4];
        float4 c = ((float4*)(sTmpP[1] + l * N_))[n4];
        const float inv = sInv[l];
        float4 r = make_float4((a.x + c.x) * inv, (a.y + c.y) * inv,
                               (a.z + c.z) * inv, (a.w + c.w) * inv);
        ((float4*)(sTmpF + l * N_))[n4] = r;
    }
    __syncthreads();

    // ---- Phase C: attn[l][m] = vq[b,l,m,:] . tmp[l], residual + LayerNorm ----
    // warp w -> row l=w. 8-lane groups: group g handles M-row m=4p+g, lane j
    // within group covers float4 j (n=4j) and 8+j (n=32+4j). Each warp
    // LDG.128 touches 4 contiguous 128B lines -> fully coalesced vq stream.
    {
        const int l = warp;
        const int g = lane >> 3;
        const int j = lane & 7;
        const float4* vq4 = (const float4*)vq + (size_t)(bl8 + l) * 64 * 16;
        const float4* tf = (const float4*)(sTmpF + l * N_);
        const float4 t0 = tf[j];
        const float4 t1 = tf[8 + j];
#pragma unroll 4
        for (int p = 0; p < 16; ++p) {
            const int m = p * 4 + g;
            float4 v0 = vq4[(size_t)m * 16 + j];
            float4 v1 = vq4[(size_t)m * 16 + 8 + j];
            float d = 0.f;
            d = fmaf(v0.x, t0.x, d); d = fmaf(v0.y, t0.y, d);
            d = fmaf(v0.z, t0.z, d); d = fmaf(v0.w, t0.w, d);
            d = fmaf(v1.x, t1.x, d); d = fmaf(v1.y, t1.y, d);
            d = fmaf(v1.z, t1.z, d); d = fmaf(v1.w, t1.w, d);
            d += __shfl_xor_sync(0xFFFFFFFFu, d, 1);
            d += __shfl_xor_sync(0xFFFFFFFFu, d, 2);
            d += __shfl_xor_sync(0xFFFFFFFFu, d, 4);
            if (j == 0) sAttn[l * M_ + m] = d;
        }
        __syncwarp();

        // LayerNorm over M=64, warp-local
        const float x0 = sQ[l * D_ + lane] + sAttn[l * M_ + lane];
        const float x1 = sQ[l * D_ + lane + 32] + sAttn[l * M_ + lane + 32];
        float s = x0 + x1, ss = x0 * x0 + x1 * x1;
#pragma unroll
        for (int o = 16; o; o >>= 1) {
            s += __shfl_xor_sync(0xFFFFFFFFu, s, o);
            ss += __shfl_xor_sync(0xFFFFFFFFu, ss, o);
        }
        const float mu = s * (1.f / 64.f);
        const float var = ss * (1.f / 64.f) - mu * mu;
        const float r = rsqrtf(var + 1e-3f);
        out[(size_t)(bl8 + l) * M_ + lane] = (x0 - mu) * r * gamma[lane] + beta[lane];
        out[(size_t)(bl8 + l) * M_ + lane + 32] =
            (x1 - mu) * r * gamma[lane + 32] + beta[lane + 32];
    }
}

// ---------------------------------------------------------------------------
extern "C" void kernel_launch(void* const* d_in, const int* in_sizes, int n_in,
                              void* d_out, int out_size) {
    const float* q     = (const float*)d_in[0];
    const float* k     = (const float*)d_in[1];
    const float* vq    = (const float*)d_in[2];
    const float* vk    = (const float*)d_in[3];
    const float* vexp  = (const float*)d_in[4];
    const float* scale = (const float*)d_in[5];
    const float* gamma = (const float*)d_in[6];
    const float* beta  = (const float*)d_in[7];
    float* out = (float*)d_out;

    vkc_kernel<<<B_ * K_, 64>>>(vk, vexp);
    attn_kernel<<<B_ * L_ / TL, 256>>>(q, k, vq, scale, gamma, beta, out);
}